// round 1
// baseline (speedup 1.0000x reference)
#include <cuda_runtime.h>
#include <math.h>

#define NREL   4
#define HEADS  4
#define CDIM   128
#define HCDIM  512
#define FDIM   128
#define DE     16
#define DRR    8
#define DED    (DE + DRR)
#define FFND   256
#define MAXN   40000
#define MAXE   150000
#define LN_EPS 1e-5f
#define SLOPE  0.2f

// ---------------- scratch (device globals; no allocation allowed) ----------------
static __device__ float        d_XL[(size_t)MAXN * NREL * HCDIM];   // [N,R,HC]
static __device__ float        d_XR[(size_t)MAXN * NREL * HCDIM];   // [N,R,HC]
static __device__ float        d_alpha[(size_t)MAXE * HEADS];       // score -> exp
static __device__ unsigned int d_menc[(size_t)MAXN * NREL * HEADS]; // encoded seg max
static __device__ float        d_denom[(size_t)MAXN * NREL * HEADS];
static __device__ float        d_agg[(size_t)MAXN * NREL * CDIM];   // head-mean agg
static __device__ float        d_h1[(size_t)MAXN * FDIM];
static __device__ float        d_mid[(size_t)MAXN * FFND];
static __device__ float        d_y[(size_t)MAXN * FDIM];
static __device__ float        d_ebase[NREL * HCDIM];               // rel_emb @ W_e[:,De:,:]

// ordered-uint encoding for float atomicMax (monotonic; 0 < enc(x) for all real x)
__device__ __forceinline__ unsigned int fenc(float f) {
    unsigned int u = __float_as_uint(f);
    return (u & 0x80000000u) ? ~u : (u | 0x80000000u);
}
__device__ __forceinline__ float fdec(unsigned int u) {
    return (u & 0x80000000u) ? __uint_as_float(u & 0x7FFFFFFFu) : __uint_as_float(~u);
}

// ---------------- init: zero accumulators each launch ----------------
__global__ void init_kernel(int N) {
    int i = blockIdx.x * blockDim.x + threadIdx.x;
    int na = N * NREL * CDIM;
    if (i < na) d_agg[i] = 0.f;
    int nm = N * NREL * HEADS;
    if (i < nm) { d_menc[i] = 0u; d_denom[i] = 0.f; }
}

// ---------------- e_base[r][hc] = rel_emb[r] @ W_e[r, De:, :] ----------------
__global__ void ebase_kernel(const float* __restrict__ rel_emb, const float* __restrict__ W_e) {
    int r = blockIdx.x;
    int hc = threadIdx.x;
    float s = 0.f;
#pragma unroll
    for (int d = 0; d < DRR; d++)
        s += rel_emb[r * DRR + d] * W_e[(r * DED + DE + d) * HCDIM + hc];
    d_ebase[r * HCDIM + hc] = s;
}

// ---------------- projection GEMMs: XL/XR[n,r,:] = h[n] @ W[r] + b[r] ----------------
// grid: (ceil(N/128), HC/128, 2*NREL). z<NREL -> lin_l, else lin_r.
__global__ __launch_bounds__(256) void proj_kernel(
    const float* __restrict__ Hm,
    const float* __restrict__ Wl, const float* __restrict__ bl,
    const float* __restrict__ Wr, const float* __restrict__ br, int N)
{
    int zr = blockIdx.z;
    int r  = zr & (NREL - 1);
    const float* W; const float* bias; float* out;
    if (zr < NREL) { W = Wl + (size_t)r * FDIM * HCDIM; bias = bl + r * HCDIM; out = d_XL; }
    else           { W = Wr + (size_t)r * FDIM * HCDIM; bias = br + r * HCDIM; out = d_XR; }

    int m0 = blockIdx.x * 128;
    int n0 = blockIdx.y * 128;

    __shared__ __align__(16) float As[8][128];
    __shared__ __align__(16) float Bs[8][128];

    int tid = threadIdx.x;
    int tx = tid & 15, ty = tid >> 4;
    float acc[8][8];
#pragma unroll
    for (int i = 0; i < 8; i++)
#pragma unroll
        for (int j = 0; j < 8; j++) acc[i][j] = 0.f;

    int aRow = tid >> 1, aCol = (tid & 1) * 4;
    int bRow = tid >> 5, bCol = (tid & 31) * 4;

    for (int k0 = 0; k0 < FDIM; k0 += 8) {
        float4 av = make_float4(0.f, 0.f, 0.f, 0.f);
        if (m0 + aRow < N)
            av = *reinterpret_cast<const float4*>(&Hm[(size_t)(m0 + aRow) * FDIM + k0 + aCol]);
        As[aCol + 0][aRow] = av.x; As[aCol + 1][aRow] = av.y;
        As[aCol + 2][aRow] = av.z; As[aCol + 3][aRow] = av.w;

        float4 bv = *reinterpret_cast<const float4*>(&W[(size_t)(k0 + bRow) * HCDIM + n0 + bCol]);
        *reinterpret_cast<float4*>(&Bs[bRow][bCol]) = bv;
        __syncthreads();

#pragma unroll
        for (int kk = 0; kk < 8; kk++) {
            float4 a0 = *reinterpret_cast<const float4*>(&As[kk][ty * 8]);
            float4 a1 = *reinterpret_cast<const float4*>(&As[kk][ty * 8 + 4]);
            float4 b0 = *reinterpret_cast<const float4*>(&Bs[kk][tx * 8]);
            float4 b1 = *reinterpret_cast<const float4*>(&Bs[kk][tx * 8 + 4]);
            float av8[8] = {a0.x, a0.y, a0.z, a0.w, a1.x, a1.y, a1.z, a1.w};
            float bv8[8] = {b0.x, b0.y, b0.z, b0.w, b1.x, b1.y, b1.z, b1.w};
#pragma unroll
            for (int i = 0; i < 8; i++)
#pragma unroll
                for (int j = 0; j < 8; j++) acc[i][j] += av8[i] * bv8[j];
        }
        __syncthreads();
    }

#pragma unroll
    for (int i = 0; i < 8; i++) {
        int row = m0 + ty * 8 + i;
        if (row < N) {
#pragma unroll
            for (int j = 0; j < 8; j++) {
                int col = n0 + tx * 8 + j;
                out[((size_t)row * NREL + r) * HCDIM + col] = acc[i][j] + bias[col];
            }
        }
    }
}

// ---------------- generic SGEMM for FFN: C = act(A[M,K] @ B[K,N] + bias) (+resid) ----------------
__global__ __launch_bounds__(256) void gemm_kernel(
    const float* __restrict__ A, const float* __restrict__ B,
    const float* __restrict__ bias, const float* __restrict__ resid,
    float* __restrict__ C, int M, int Nn, int K, int act)
{
    int m0 = blockIdx.x * 128;
    int n0 = blockIdx.y * 128;

    __shared__ __align__(16) float As[8][128];
    __shared__ __align__(16) float Bs[8][128];

    int tid = threadIdx.x;
    int tx = tid & 15, ty = tid >> 4;
    float acc[8][8];
#pragma unroll
    for (int i = 0; i < 8; i++)
#pragma unroll
        for (int j = 0; j < 8; j++) acc[i][j] = 0.f;

    int aRow = tid >> 1, aCol = (tid & 1) * 4;
    int bRow = tid >> 5, bCol = (tid & 31) * 4;

    for (int k0 = 0; k0 < K; k0 += 8) {
        float4 av = make_float4(0.f, 0.f, 0.f, 0.f);
        if (m0 + aRow < M)
            av = *reinterpret_cast<const float4*>(&A[(size_t)(m0 + aRow) * K + k0 + aCol]);
        As[aCol + 0][aRow] = av.x; As[aCol + 1][aRow] = av.y;
        As[aCol + 2][aRow] = av.z; As[aCol + 3][aRow] = av.w;

        float4 bv = *reinterpret_cast<const float4*>(&B[(size_t)(k0 + bRow) * Nn + n0 + bCol]);
        *reinterpret_cast<float4*>(&Bs[bRow][bCol]) = bv;
        __syncthreads();

#pragma unroll
        for (int kk = 0; kk < 8; kk++) {
            float4 a0 = *reinterpret_cast<const float4*>(&As[kk][ty * 8]);
            float4 a1 = *reinterpret_cast<const float4*>(&As[kk][ty * 8 + 4]);
            float4 b0 = *reinterpret_cast<const float4*>(&Bs[kk][tx * 8]);
            float4 b1 = *reinterpret_cast<const float4*>(&Bs[kk][tx * 8 + 4]);
            float av8[8] = {a0.x, a0.y, a0.z, a0.w, a1.x, a1.y, a1.z, a1.w};
            float bv8[8] = {b0.x, b0.y, b0.z, b0.w, b1.x, b1.y, b1.z, b1.w};
#pragma unroll
            for (int i = 0; i < 8; i++)
#pragma unroll
                for (int j = 0; j < 8; j++) acc[i][j] += av8[i] * bv8[j];
        }
        __syncthreads();
    }

#pragma unroll
    for (int i = 0; i < 8; i++) {
        int row = m0 + ty * 8 + i;
        if (row < M) {
#pragma unroll
            for (int j = 0; j < 8; j++) {
                int col = n0 + tx * 8 + j;
                float v = acc[i][j] + bias[col];
                if (act == 1) v = v / (1.f + expf(-v));          // silu
                if (resid) v += resid[(size_t)row * Nn + col];
                C[(size_t)row * Nn + col] = v;
            }
        }
    }
}

// ---------------- per-edge attention scores + segment max ----------------
// one warp per edge; lane handles 4 consecutive hc per head-chunk (i == head).
__global__ void score_kernel(
    const int* __restrict__ src, const int* __restrict__ dst, const int* __restrict__ etype,
    const float* __restrict__ eattr, const float* __restrict__ W_e,
    const float* __restrict__ att, int E)
{
    int warp = (blockIdx.x * blockDim.x + threadIdx.x) >> 5;
    int lane = threadIdx.x & 31;
    if (warp >= E) return;
    int e = warp;
    int r = etype[e];
    int s = src[e];
    int d = dst[e];

    const float* xl = d_XL + ((size_t)s * NREL + r) * HCDIM;
    const float* xr = d_XR + ((size_t)d * NREL + r) * HCDIM;

    float ea[DE];
#pragma unroll
    for (int k = 0; k < DE; k++) ea[k] = __ldg(&eattr[(size_t)e * DE + k]);

    float hs[HEADS];
#pragma unroll
    for (int i = 0; i < HEADS; i++) {
        int hc = i * 128 + lane * 4;
        float4 vl = *reinterpret_cast<const float4*>(&xl[hc]);
        float4 vr = *reinterpret_cast<const float4*>(&xr[hc]);
        float4 ef = *reinterpret_cast<const float4*>(&d_ebase[r * HCDIM + hc]);
#pragma unroll
        for (int k = 0; k < DE; k++) {
            float4 w = *reinterpret_cast<const float4*>(&W_e[(size_t)(r * DED + k) * HCDIM + hc]);
            ef.x += ea[k] * w.x; ef.y += ea[k] * w.y;
            ef.z += ea[k] * w.z; ef.w += ea[k] * w.w;
        }
        float x0 = vl.x + vr.x + ef.x; x0 = x0 > 0.f ? x0 : SLOPE * x0;
        float x1 = vl.y + vr.y + ef.y; x1 = x1 > 0.f ? x1 : SLOPE * x1;
        float x2 = vl.z + vr.z + ef.z; x2 = x2 > 0.f ? x2 : SLOPE * x2;
        float x3 = vl.w + vr.w + ef.w; x3 = x3 > 0.f ? x3 : SLOPE * x3;
        float4 a = *reinterpret_cast<const float4*>(&att[r * HCDIM + hc]);
        hs[i] = x0 * a.x + x1 * a.y + x2 * a.z + x3 * a.w;
    }
#pragma unroll
    for (int o = 16; o; o >>= 1) {
#pragma unroll
        for (int i = 0; i < HEADS; i++) hs[i] += __shfl_xor_sync(0xffffffffu, hs[i], o);
    }
    if (lane == 0) {
        int segb = (d * NREL + r) * HEADS;
#pragma unroll
        for (int h = 0; h < HEADS; h++) {
            d_alpha[(size_t)e * HEADS + h] = hs[h];
            atomicMax(&d_menc[segb + h], fenc(hs[h]));
        }
    }
}

// ---------------- exp(score - max), accumulate denom ----------------
__global__ void expsum_kernel(const int* __restrict__ dst, const int* __restrict__ etype, int E) {
    int idx = blockIdx.x * blockDim.x + threadIdx.x;
    if (idx >= E * HEADS) return;
    int e = idx >> 2;
    int h = idx & 3;
    int r = etype[e];
    int d = dst[e];
    int seg = (d * NREL + r) * HEADS + h;
    float m = fdec(d_menc[seg]);
    float a = expf(d_alpha[idx] - m);
    d_alpha[idx] = a;
    atomicAdd(&d_denom[seg], a);
}

// ---------------- aggregate: agg[dst,r,c] += (1/H) * sum_h alpha * xl_e[h,c] ----------------
__global__ void agg_kernel(const int* __restrict__ src, const int* __restrict__ dst,
                           const int* __restrict__ etype, int E)
{
    int warp = (blockIdx.x * blockDim.x + threadIdx.x) >> 5;
    int lane = threadIdx.x & 31;
    if (warp >= E) return;
    int e = warp;
    int r = etype[e];
    int s = src[e];
    int d = dst[e];
    int segb = (d * NREL + r) * HEADS;

    float al[HEADS];
#pragma unroll
    for (int h = 0; h < HEADS; h++)
        al[h] = d_alpha[(size_t)e * HEADS + h] / d_denom[segb + h] * (1.f / HEADS);

    const float* xl = d_XL + ((size_t)s * NREL + r) * HCDIM;
    int c0 = lane * 4;
    float4 acc = make_float4(0.f, 0.f, 0.f, 0.f);
#pragma unroll
    for (int h = 0; h < HEADS; h++) {
        float4 v = *reinterpret_cast<const float4*>(&xl[h * CDIM + c0]);
        acc.x += al[h] * v.x; acc.y += al[h] * v.y;
        acc.z += al[h] * v.z; acc.w += al[h] * v.w;
    }
    float* outp = d_agg + ((size_t)d * NREL + r) * CDIM + c0;
    atomicAdd(outp + 0, acc.x);
    atomicAdd(outp + 1, acc.y);
    atomicAdd(outp + 2, acc.z);
    atomicAdd(outp + 3, acc.w);
}

// ---------------- gated fusion over relations + residual + LayerNorm1 ----------------
__global__ void fuse1_kernel(const float* __restrict__ hin, const float* __restrict__ relbias,
                             const float* __restrict__ gate, const float* __restrict__ g1,
                             const float* __restrict__ bt1, int N)
{
    int n = blockIdx.x;
    if (n >= N) return;
    int c = threadIdx.x;

    float gv0 = __ldg(&gate[0]), gv1 = __ldg(&gate[1]), gv2 = __ldg(&gate[2]), gv3 = __ldg(&gate[3]);
    float gm = fmaxf(fmaxf(gv0, gv1), fmaxf(gv2, gv3));
    float e0 = expf(gv0 - gm), e1 = expf(gv1 - gm), e2 = expf(gv2 - gm), e3 = expf(gv3 - gm);
    float inv = 1.f / (e0 + e1 + e2 + e3);

    size_t ab = (size_t)n * NREL * CDIM;
    float t = hin[(size_t)n * FDIM + c]
            + e0 * inv * (d_agg[ab + 0 * CDIM + c] + relbias[0 * CDIM + c])
            + e1 * inv * (d_agg[ab + 1 * CDIM + c] + relbias[1 * CDIM + c])
            + e2 * inv * (d_agg[ab + 2 * CDIM + c] + relbias[2 * CDIM + c])
            + e3 * inv * (d_agg[ab + 3 * CDIM + c] + relbias[3 * CDIM + c]);

    __shared__ float sh1[4], sh2[4];
    float s1 = t, s2 = t * t;
#pragma unroll
    for (int o = 16; o; o >>= 1) {
        s1 += __shfl_xor_sync(0xffffffffu, s1, o);
        s2 += __shfl_xor_sync(0xffffffffu, s2, o);
    }
    if ((threadIdx.x & 31) == 0) { sh1[threadIdx.x >> 5] = s1; sh2[threadIdx.x >> 5] = s2; }
    __syncthreads();
    s1 = sh1[0] + sh1[1] + sh1[2] + sh1[3];
    s2 = sh2[0] + sh2[1] + sh2[2] + sh2[3];
    float mu = s1 * (1.f / FDIM);
    float var = s2 * (1.f / FDIM) - mu * mu;
    d_h1[(size_t)n * FDIM + c] = (t - mu) * rsqrtf(var + LN_EPS) * g1[c] + bt1[c];
}

// ---------------- final LayerNorm2 -> out ----------------
__global__ void ln2_kernel(const float* __restrict__ g2, const float* __restrict__ bt2,
                           float* __restrict__ out, int N)
{
    int n = blockIdx.x;
    if (n >= N) return;
    int c = threadIdx.x;
    float t = d_y[(size_t)n * FDIM + c];

    __shared__ float sh1[4], sh2[4];
    float s1 = t, s2 = t * t;
#pragma unroll
    for (int o = 16; o; o >>= 1) {
        s1 += __shfl_xor_sync(0xffffffffu, s1, o);
        s2 += __shfl_xor_sync(0xffffffffu, s2, o);
    }
    if ((threadIdx.x & 31) == 0) { sh1[threadIdx.x >> 5] = s1; sh2[threadIdx.x >> 5] = s2; }
    __syncthreads();
    s1 = sh1[0] + sh1[1] + sh1[2] + sh1[3];
    s2 = sh2[0] + sh2[1] + sh2[2] + sh2[3];
    float mu = s1 * (1.f / FDIM);
    float var = s2 * (1.f / FDIM) - mu * mu;
    out[(size_t)n * FDIM + c] = (t - mu) * rsqrtf(var + LN_EPS) * g2[c] + bt2[c];
}

// ---------------- host launcher ----------------
extern "C" void kernel_launch(void* const* d_in, const int* in_sizes, int n_in,
                              void* d_out, int out_size)
{
    const float* h       = (const float*)d_in[0];
    const int*   eidx    = (const int*)  d_in[1];
    const float* eattr   = (const float*)d_in[2];
    const int*   etype   = (const int*)  d_in[3];
    const float* rel_emb = (const float*)d_in[4];
    const float* W_l     = (const float*)d_in[5];
    const float* b_l     = (const float*)d_in[6];
    const float* W_r     = (const float*)d_in[7];
    const float* b_r     = (const float*)d_in[8];
    const float* W_e     = (const float*)d_in[9];
    const float* att     = (const float*)d_in[10];
    const float* bias    = (const float*)d_in[11];
    const float* gate    = (const float*)d_in[12];
    const float* g1      = (const float*)d_in[13];
    const float* bt1     = (const float*)d_in[14];
    const float* g2      = (const float*)d_in[15];
    const float* bt2     = (const float*)d_in[16];
    const float* Wf1     = (const float*)d_in[17];
    const float* bf1     = (const float*)d_in[18];
    const float* Wf2     = (const float*)d_in[19];
    const float* bf2     = (const float*)d_in[20];
    float* out = (float*)d_out;

    int N = in_sizes[0] / FDIM;
    int E = in_sizes[3];
    const int* src = eidx;
    const int* dst = eidx + E;

    void *ph1 = nullptr, *pmid = nullptr, *py = nullptr;
    cudaGetSymbolAddress(&ph1, d_h1);
    cudaGetSymbolAddress(&pmid, d_mid);
    cudaGetSymbolAddress(&py, d_y);

    // 1. zero accumulators
    {
        int na = N * NREL * CDIM;
        init_kernel<<<(na + 255) / 256, 256>>>(N);
    }
    // 2. relation-embedding part of lin_edge (tiny)
    ebase_kernel<<<NREL, HCDIM>>>(rel_emb, W_e);
    // 3. projections XL / XR  (dominant GEMMs)
    {
        dim3 grid((N + 127) / 128, HCDIM / 128, 2 * NREL);
        proj_kernel<<<grid, 256>>>(h, W_l, b_l, W_r, b_r, N);
    }
    // 4. attention scores + segment max
    score_kernel<<<(E + 7) / 8, 256>>>(src, dst, etype, eattr, W_e, att, E);
    // 5. exp + denom
    expsum_kernel<<<(E * HEADS + 255) / 256, 256>>>(dst, etype, E);
    // 6. weighted aggregation (folds head-mean)
    agg_kernel<<<(E + 7) / 8, 256>>>(src, dst, etype, E);
    // 7. gate fusion + residual + LN1
    fuse1_kernel<<<N, 128>>>(h, bias, gate, g1, bt1, N);
    // 8. FFN up (silu)
    {
        dim3 grid((N + 127) / 128, FFND / 128);
        gemm_kernel<<<grid, 256>>>((const float*)ph1, Wf1, bf1, nullptr, (float*)pmid,
                                   N, FFND, FDIM, 1);
    }
    // 9. FFN down + residual (pre-LN)
    {
        dim3 grid((N + 127) / 128, FDIM / 128);
        gemm_kernel<<<grid, 256>>>((const float*)pmid, Wf2, bf2, (const float*)ph1, (float*)py,
                                   N, FDIM, FFND, 0);
    }
    // 10. LN2 -> out
    ln2_kernel<<<N, 128>>>(g2, bt2, out, N);
}

// round 2
// speedup vs baseline: 1.7816x; 1.7816x over previous
#include <cuda_runtime.h>
#include <math.h>

#define NREL   4
#define HEADS  4
#define CDIM   128
#define HCDIM  512
#define FDIM   128
#define DE     16
#define DRR    8
#define DED    (DE + DRR)
#define FFND   256
#define MAXN   40000
#define MAXE   150000
#define LN_EPS 1e-5f
#define SLOPE  0.2f

// ---------------- scratch (device globals; no allocation allowed) ----------------
static __device__ float        d_XL[(size_t)MAXN * NREL * HCDIM];   // [N,R,HC]
static __device__ float        d_XR[(size_t)MAXN * NREL * HCDIM];   // [N,R,HC]
static __device__ float        d_alpha[(size_t)MAXE * HEADS];       // score -> exp
static __device__ unsigned int d_menc[(size_t)MAXN * NREL * HEADS]; // encoded seg max
static __device__ float        d_denom[(size_t)MAXN * NREL * HEADS];
static __device__ float        d_agg[(size_t)MAXN * NREL * CDIM];   // head-mean agg
static __device__ float        d_h1[(size_t)MAXN * FDIM];
static __device__ float        d_mid[(size_t)MAXN * FFND];
static __device__ float        d_y[(size_t)MAXN * FDIM];
static __device__ float        d_ebase[NREL * HCDIM];               // rel_emb @ W_e[:,De:,:]

// ordered-uint encoding for float atomicMax
__device__ __forceinline__ unsigned int fenc(float f) {
    unsigned int u = __float_as_uint(f);
    return (u & 0x80000000u) ? ~u : (u | 0x80000000u);
}
__device__ __forceinline__ float fdec(unsigned int u) {
    return (u & 0x80000000u) ? __uint_as_float(u & 0x7FFFFFFFu) : __uint_as_float(~u);
}

__device__ __forceinline__ unsigned int f2tf32(float f) {
    unsigned int u;
    asm("cvt.rna.tf32.f32 %0, %1;" : "=r"(u) : "f"(f));
    return u;
}

__device__ __forceinline__ void mma_tf32(float c[4],
                                         unsigned a0, unsigned a1, unsigned a2, unsigned a3,
                                         unsigned b0, unsigned b1) {
    asm volatile(
        "mma.sync.aligned.m16n8k8.row.col.f32.tf32.tf32.f32 "
        "{%0,%1,%2,%3}, {%4,%5,%6,%7}, {%8,%9}, {%0,%1,%2,%3};"
        : "+f"(c[0]), "+f"(c[1]), "+f"(c[2]), "+f"(c[3])
        : "r"(a0), "r"(a1), "r"(a2), "r"(a3), "r"(b0), "r"(b1));
}

// ---------------- init ----------------
__global__ void init_kernel(int N) {
    int i = blockIdx.x * blockDim.x + threadIdx.x;
    int na = N * NREL * CDIM;
    if (i < na) d_agg[i] = 0.f;
    int nm = N * NREL * HEADS;
    if (i < nm) { d_menc[i] = 0u; d_denom[i] = 0.f; }
}

// ---------------- e_base[r][hc] = rel_emb[r] @ W_e[r, De:, :] ----------------
__global__ void ebase_kernel(const float* __restrict__ rel_emb, const float* __restrict__ W_e) {
    int r = blockIdx.x;
    int hc = threadIdx.x;
    float s = 0.f;
#pragma unroll
    for (int d = 0; d < DRR; d++)
        s += rel_emb[r * DRR + d] * W_e[(r * DED + DE + d) * HCDIM + hc];
    d_ebase[r * HCDIM + hc] = s;
}

// ---------------- generic tf32 tensor-core GEMM ----------------
// C[M,Nn] = act(A[M,K] @ B[K,Nn] + bias) (+resid).  Tiles: BM=128, BN=128, BK=16.
// 256 threads = 8 warps, layout 4(M) x 2(N); per-warp 32x64 via 2x8 m16n8k8 tiles.
#define BK 16
#define AST 20
#define BST 136
__global__ __launch_bounds__(256) void gemm_tf32(
    const float* __restrict__ A, int lda,
    const float* __restrict__ B, int ldb,
    const float* __restrict__ bias,
    const float* __restrict__ resid,
    float* __restrict__ C, int ldc,
    int M, int Nn, int K, int act)
{
    __shared__ float As[128][AST];   // 16 k cols used, padded
    __shared__ float Bs[BK][BST];    // 128 n cols used, padded

    int tid = threadIdx.x;
    int wid = tid >> 5, lane = tid & 31;
    int wm0 = (wid & 3) * 32;
    int wn0 = (wid >> 2) * 64;
    int gid = lane >> 2, tig = lane & 3;

    int m0 = blockIdx.x * 128;
    int n0 = blockIdx.y * 128;

    float acc[2][8][4];
#pragma unroll
    for (int mi = 0; mi < 2; mi++)
#pragma unroll
        for (int ni = 0; ni < 8; ni++)
#pragma unroll
            for (int q = 0; q < 4; q++) acc[mi][ni][q] = 0.f;

    for (int k0 = 0; k0 < K; k0 += BK) {
        // A tile: 128x16 floats = 512 float4, 2 per thread
#pragma unroll
        for (int i = 0; i < 2; i++) {
            int f = tid + i * 256;
            int row = f >> 2, cv = (f & 3) * 4;
            float4 v = make_float4(0.f, 0.f, 0.f, 0.f);
            if (m0 + row < M)
                v = *reinterpret_cast<const float4*>(&A[(size_t)(m0 + row) * lda + k0 + cv]);
            uint4 t = make_uint4(f2tf32(v.x), f2tf32(v.y), f2tf32(v.z), f2tf32(v.w));
            *reinterpret_cast<uint4*>(&As[row][cv]) = t;
        }
        // B tile: 16x128 floats = 512 float4, 2 per thread
#pragma unroll
        for (int i = 0; i < 2; i++) {
            int f = tid + i * 256;
            int kr = f >> 5, nv = (f & 31) * 4;
            float4 v = *reinterpret_cast<const float4*>(&B[(size_t)(k0 + kr) * ldb + n0 + nv]);
            uint4 t = make_uint4(f2tf32(v.x), f2tf32(v.y), f2tf32(v.z), f2tf32(v.w));
            *reinterpret_cast<uint4*>(&Bs[kr][nv]) = t;
        }
        __syncthreads();

#pragma unroll
        for (int ks = 0; ks < 2; ks++) {
            int kk = ks * 8;
            unsigned a[2][4];
#pragma unroll
            for (int mi = 0; mi < 2; mi++) {
                int row = wm0 + mi * 16 + gid;
                a[mi][0] = __float_as_uint(As[row    ][kk + tig    ]);
                a[mi][1] = __float_as_uint(As[row + 8][kk + tig    ]);
                a[mi][2] = __float_as_uint(As[row    ][kk + tig + 4]);
                a[mi][3] = __float_as_uint(As[row + 8][kk + tig + 4]);
            }
            unsigned b[8][2];
#pragma unroll
            for (int ni = 0; ni < 8; ni++) {
                int col = wn0 + ni * 8 + gid;
                b[ni][0] = __float_as_uint(Bs[kk + tig    ][col]);
                b[ni][1] = __float_as_uint(Bs[kk + tig + 4][col]);
            }
#pragma unroll
            for (int mi = 0; mi < 2; mi++)
#pragma unroll
                for (int ni = 0; ni < 8; ni++)
                    mma_tf32(acc[mi][ni], a[mi][0], a[mi][1], a[mi][2], a[mi][3],
                             b[ni][0], b[ni][1]);
        }
        __syncthreads();
    }

    // epilogue
#pragma unroll
    for (int mi = 0; mi < 2; mi++) {
#pragma unroll
        for (int ni = 0; ni < 8; ni++) {
            int row = m0 + wm0 + mi * 16 + gid;
            int col = n0 + wn0 + ni * 8 + tig * 2;
            float bv0 = bias[col], bv1 = bias[col + 1];
#pragma unroll
            for (int half = 0; half < 2; half++) {
                int rr = row + half * 8;
                if (rr < M) {
                    float v0 = acc[mi][ni][half * 2 + 0] + bv0;
                    float v1 = acc[mi][ni][half * 2 + 1] + bv1;
                    if (act == 1) {
                        v0 = v0 / (1.f + expf(-v0));
                        v1 = v1 / (1.f + expf(-v1));
                    }
                    if (resid) {
                        v0 += resid[(size_t)rr * Nn + col];
                        v1 += resid[(size_t)rr * Nn + col + 1];
                    }
                    *reinterpret_cast<float2*>(&C[(size_t)rr * ldc + col]) = make_float2(v0, v1);
                }
            }
        }
    }
}

// ---------------- per-edge attention scores + segment max ----------------
__global__ void score_kernel(
    const int* __restrict__ src, const int* __restrict__ dst, const int* __restrict__ etype,
    const float* __restrict__ eattr, const float* __restrict__ W_e,
    const float* __restrict__ att, int E)
{
    int warp = (blockIdx.x * blockDim.x + threadIdx.x) >> 5;
    int lane = threadIdx.x & 31;
    if (warp >= E) return;
    int e = warp;
    int r = etype[e];
    int s = src[e];
    int d = dst[e];

    const float* xl = d_XL + ((size_t)s * NREL + r) * HCDIM;
    const float* xr = d_XR + ((size_t)d * NREL + r) * HCDIM;

    float ea[DE];
#pragma unroll
    for (int k = 0; k < DE; k++) ea[k] = __ldg(&eattr[(size_t)e * DE + k]);

    float hs[HEADS];
#pragma unroll
    for (int i = 0; i < HEADS; i++) {
        int hc = i * 128 + lane * 4;
        float4 vl = *reinterpret_cast<const float4*>(&xl[hc]);
        float4 vr = *reinterpret_cast<const float4*>(&xr[hc]);
        float4 ef = *reinterpret_cast<const float4*>(&d_ebase[r * HCDIM + hc]);
#pragma unroll
        for (int k = 0; k < DE; k++) {
            float4 w = *reinterpret_cast<const float4*>(&W_e[(size_t)(r * DED + k) * HCDIM + hc]);
            ef.x += ea[k] * w.x; ef.y += ea[k] * w.y;
            ef.z += ea[k] * w.z; ef.w += ea[k] * w.w;
        }
        float x0 = vl.x + vr.x + ef.x; x0 = x0 > 0.f ? x0 : SLOPE * x0;
        float x1 = vl.y + vr.y + ef.y; x1 = x1 > 0.f ? x1 : SLOPE * x1;
        float x2 = vl.z + vr.z + ef.z; x2 = x2 > 0.f ? x2 : SLOPE * x2;
        float x3 = vl.w + vr.w + ef.w; x3 = x3 > 0.f ? x3 : SLOPE * x3;
        float4 a = *reinterpret_cast<const float4*>(&att[r * HCDIM + hc]);
        hs[i] = x0 * a.x + x1 * a.y + x2 * a.z + x3 * a.w;
    }
#pragma unroll
    for (int o = 16; o; o >>= 1) {
#pragma unroll
        for (int i = 0; i < HEADS; i++) hs[i] += __shfl_xor_sync(0xffffffffu, hs[i], o);
    }
    if (lane == 0) {
        int segb = (d * NREL + r) * HEADS;
#pragma unroll
        for (int h = 0; h < HEADS; h++) {
            d_alpha[(size_t)e * HEADS + h] = hs[h];
            atomicMax(&d_menc[segb + h], fenc(hs[h]));
        }
    }
}

// ---------------- exp(score - max), accumulate denom ----------------
__global__ void expsum_kernel(const int* __restrict__ dst, const int* __restrict__ etype, int E) {
    int idx = blockIdx.x * blockDim.x + threadIdx.x;
    if (idx >= E * HEADS) return;
    int e = idx >> 2;
    int h = idx & 3;
    int r = etype[e];
    int d = dst[e];
    int seg = (d * NREL + r) * HEADS + h;
    float m = fdec(d_menc[seg]);
    float a = expf(d_alpha[idx] - m);
    d_alpha[idx] = a;
    atomicAdd(&d_denom[seg], a);
}

// ---------------- aggregate ----------------
__global__ void agg_kernel(const int* __restrict__ src, const int* __restrict__ dst,
                           const int* __restrict__ etype, int E)
{
    int warp = (blockIdx.x * blockDim.x + threadIdx.x) >> 5;
    int lane = threadIdx.x & 31;
    if (warp >= E) return;
    int e = warp;
    int r = etype[e];
    int s = src[e];
    int d = dst[e];
    int segb = (d * NREL + r) * HEADS;

    float al[HEADS];
#pragma unroll
    for (int h = 0; h < HEADS; h++)
        al[h] = d_alpha[(size_t)e * HEADS + h] / d_denom[segb + h] * (1.f / HEADS);

    const float* xl = d_XL + ((size_t)s * NREL + r) * HCDIM;
    int c0 = lane * 4;
    float4 acc = make_float4(0.f, 0.f, 0.f, 0.f);
#pragma unroll
    for (int h = 0; h < HEADS; h++) {
        float4 v = *reinterpret_cast<const float4*>(&xl[h * CDIM + c0]);
        acc.x += al[h] * v.x; acc.y += al[h] * v.y;
        acc.z += al[h] * v.z; acc.w += al[h] * v.w;
    }
    float* outp = d_agg + ((size_t)d * NREL + r) * CDIM + c0;
    atomicAdd(outp + 0, acc.x);
    atomicAdd(outp + 1, acc.y);
    atomicAdd(outp + 2, acc.z);
    atomicAdd(outp + 3, acc.w);
}

// ---------------- gated fusion + residual + LayerNorm1 ----------------
__global__ void fuse1_kernel(const float* __restrict__ hin, const float* __restrict__ relbias,
                             const float* __restrict__ gate, const float* __restrict__ g1,
                             const float* __restrict__ bt1, int N)
{
    int n = blockIdx.x;
    if (n >= N) return;
    int c = threadIdx.x;

    float gv0 = __ldg(&gate[0]), gv1 = __ldg(&gate[1]), gv2 = __ldg(&gate[2]), gv3 = __ldg(&gate[3]);
    float gm = fmaxf(fmaxf(gv0, gv1), fmaxf(gv2, gv3));
    float e0 = expf(gv0 - gm), e1 = expf(gv1 - gm), e2 = expf(gv2 - gm), e3 = expf(gv3 - gm);
    float inv = 1.f / (e0 + e1 + e2 + e3);

    size_t ab = (size_t)n * NREL * CDIM;
    float t = hin[(size_t)n * FDIM + c]
            + e0 * inv * (d_agg[ab + 0 * CDIM + c] + relbias[0 * CDIM + c])
            + e1 * inv * (d_agg[ab + 1 * CDIM + c] + relbias[1 * CDIM + c])
            + e2 * inv * (d_agg[ab + 2 * CDIM + c] + relbias[2 * CDIM + c])
            + e3 * inv * (d_agg[ab + 3 * CDIM + c] + relbias[3 * CDIM + c]);

    __shared__ float sh1[4], sh2[4];
    float s1 = t, s2 = t * t;
#pragma unroll
    for (int o = 16; o; o >>= 1) {
        s1 += __shfl_xor_sync(0xffffffffu, s1, o);
        s2 += __shfl_xor_sync(0xffffffffu, s2, o);
    }
    if ((threadIdx.x & 31) == 0) { sh1[threadIdx.x >> 5] = s1; sh2[threadIdx.x >> 5] = s2; }
    __syncthreads();
    s1 = sh1[0] + sh1[1] + sh1[2] + sh1[3];
    s2 = sh2[0] + sh2[1] + sh2[2] + sh2[3];
    float mu = s1 * (1.f / FDIM);
    float var = s2 * (1.f / FDIM) - mu * mu;
    d_h1[(size_t)n * FDIM + c] = (t - mu) * rsqrtf(var + LN_EPS) * g1[c] + bt1[c];
}

// ---------------- final LayerNorm2 -> out ----------------
__global__ void ln2_kernel(const float* __restrict__ g2, const float* __restrict__ bt2,
                           float* __restrict__ out, int N)
{
    int n = blockIdx.x;
    if (n >= N) return;
    int c = threadIdx.x;
    float t = d_y[(size_t)n * FDIM + c];

    __shared__ float sh1[4], sh2[4];
    float s1 = t, s2 = t * t;
#pragma unroll
    for (int o = 16; o; o >>= 1) {
        s1 += __shfl_xor_sync(0xffffffffu, s1, o);
        s2 += __shfl_xor_sync(0xffffffffu, s2, o);
    }
    if ((threadIdx.x & 31) == 0) { sh1[threadIdx.x >> 5] = s1; sh2[threadIdx.x >> 5] = s2; }
    __syncthreads();
    s1 = sh1[0] + sh1[1] + sh1[2] + sh1[3];
    s2 = sh2[0] + sh2[1] + sh2[2] + sh2[3];
    float mu = s1 * (1.f / FDIM);
    float var = s2 * (1.f / FDIM) - mu * mu;
    out[(size_t)n * FDIM + c] = (t - mu) * rsqrtf(var + LN_EPS) * g2[c] + bt2[c];
}

// ---------------- host launcher ----------------
extern "C" void kernel_launch(void* const* d_in, const int* in_sizes, int n_in,
                              void* d_out, int out_size)
{
    const float* h       = (const float*)d_in[0];
    const int*   eidx    = (const int*)  d_in[1];
    const float* eattr   = (const float*)d_in[2];
    const int*   etype   = (const int*)  d_in[3];
    const float* rel_emb = (const float*)d_in[4];
    const float* W_l     = (const float*)d_in[5];
    const float* b_l     = (const float*)d_in[6];
    const float* W_r     = (const float*)d_in[7];
    const float* b_r     = (const float*)d_in[8];
    const float* W_e     = (const float*)d_in[9];
    const float* att     = (const float*)d_in[10];
    const float* bias    = (const float*)d_in[11];
    const float* gate    = (const float*)d_in[12];
    const float* g1      = (const float*)d_in[13];
    const float* bt1     = (const float*)d_in[14];
    const float* g2      = (const float*)d_in[15];
    const float* bt2     = (const float*)d_in[16];
    const float* Wf1     = (const float*)d_in[17];
    const float* bf1     = (const float*)d_in[18];
    const float* Wf2     = (const float*)d_in[19];
    const float* bf2     = (const float*)d_in[20];
    float* out = (float*)d_out;

    int N = in_sizes[0] / FDIM;
    int E = in_sizes[3];
    const int* src = eidx;
    const int* dst = eidx + E;

    void *ph1 = nullptr, *pmid = nullptr, *py = nullptr, *pXL = nullptr, *pXR = nullptr;
    cudaGetSymbolAddress(&ph1, d_h1);
    cudaGetSymbolAddress(&pmid, d_mid);
    cudaGetSymbolAddress(&py, d_y);
    cudaGetSymbolAddress(&pXL, d_XL);
    cudaGetSymbolAddress(&pXR, d_XR);

    // 1. zero accumulators
    {
        int na = N * NREL * CDIM;
        init_kernel<<<(na + 255) / 256, 256>>>(N);
    }
    // 2. relation-embedding part of lin_edge (tiny)
    ebase_kernel<<<NREL, HCDIM>>>(rel_emb, W_e);
    // 3. projections XL / XR via tensor-core tf32 GEMMs (8 launches)
    {
        dim3 grid((N + 127) / 128, HCDIM / 128);
        for (int z = 0; z < 8; z++) {
            int r = z & 3;
            const float* W  = (z < 4 ? W_l : W_r) + (size_t)r * FDIM * HCDIM;
            const float* bb = (z < 4 ? b_l : b_r) + r * HCDIM;
            float* Cp = (float*)(z < 4 ? pXL : pXR) + r * HCDIM;
            gemm_tf32<<<grid, 256>>>(h, FDIM, W, HCDIM, bb, nullptr,
                                     Cp, NREL * HCDIM, N, HCDIM, FDIM, 0);
        }
    }
    // 4. attention scores + segment max
    score_kernel<<<(E + 7) / 8, 256>>>(src, dst, etype, eattr, W_e, att, E);
    // 5. exp + denom
    expsum_kernel<<<(E * HEADS + 255) / 256, 256>>>(dst, etype, E);
    // 6. weighted aggregation
    agg_kernel<<<(E + 7) / 8, 256>>>(src, dst, etype, E);
    // 7. gate fusion + residual + LN1
    fuse1_kernel<<<N, 128>>>(h, bias, gate, g1, bt1, N);
    // 8. FFN up (silu) — tf32
    {
        dim3 grid((N + 127) / 128, FFND / 128);
        gemm_tf32<<<grid, 256>>>((const float*)ph1, FDIM, Wf1, FFND, bf1, nullptr,
                                 (float*)pmid, FFND, N, FFND, FDIM, 1);
    }
    // 9. FFN down + residual — tf32
    {
        dim3 grid((N + 127) / 128, FDIM / 128);
        gemm_tf32<<<grid, 256>>>((const float*)pmid, FFND, Wf2, FDIM, bf2, (const float*)ph1,
                                 (float*)py, FDIM, N, FDIM, FFND, 0);
    }
    // 10. LN2 -> out
    ln2_kernel<<<N, 128>>>(g2, bt2, out, N);
}

// round 3
// speedup vs baseline: 2.1183x; 1.1890x over previous
#include <cuda_runtime.h>
#include <math.h>

#define NREL   4
#define HEADS  4
#define CDIM   128
#define HCDIM  512
#define FDIM   128
#define DE     16
#define DRR    8
#define DED    (DE + DRR)
#define FFND   256
#define MAXN   40000
#define MAXE   150000
#define PMAX   (MAXE + 512)
#define LN_EPS 1e-5f
#define SLOPE  0.2f

// ---------------- scratch ----------------
static __device__ float        d_XL[(size_t)MAXN * NREL * HCDIM];
static __device__ float        d_XR[(size_t)MAXN * NREL * HCDIM];
static __device__ float        d_efeat[(size_t)PMAX * HCDIM];
static __device__ float        d_eattrs[(size_t)PMAX * DE];
static __device__ int          d_srcs[PMAX];
static __device__ int          d_dsts[PMAX];
static __device__ int          d_etys[PMAX];
static __device__ int          d_cnt[NREL];
static __device__ int          d_off[NREL + 1];
static __device__ int          d_pos[NREL];
static __device__ float        d_alpha[(size_t)PMAX * HEADS];
static __device__ unsigned int d_menc[(size_t)MAXN * NREL * HEADS];
static __device__ float        d_denom[(size_t)MAXN * NREL * HEADS];
static __device__ float        d_agg[(size_t)MAXN * NREL * CDIM];
static __device__ float        d_h1[(size_t)MAXN * FDIM];
static __device__ float        d_mid[(size_t)MAXN * FFND];
static __device__ float        d_y[(size_t)MAXN * FDIM];
static __device__ float        d_ebase[NREL * HCDIM];

__device__ __forceinline__ unsigned int fenc(float f) {
    unsigned int u = __float_as_uint(f);
    return (u & 0x80000000u) ? ~u : (u | 0x80000000u);
}
__device__ __forceinline__ float fdec(unsigned int u) {
    return (u & 0x80000000u) ? __uint_as_float(u & 0x7FFFFFFFu) : __uint_as_float(~u);
}

__device__ __forceinline__ void mma_tf32(float c[4],
                                         unsigned a0, unsigned a1, unsigned a2, unsigned a3,
                                         unsigned b0, unsigned b1) {
    asm volatile(
        "mma.sync.aligned.m16n8k8.row.col.f32.tf32.tf32.f32 "
        "{%0,%1,%2,%3}, {%4,%5,%6,%7}, {%8,%9}, {%0,%1,%2,%3};"
        : "+f"(c[0]), "+f"(c[1]), "+f"(c[2]), "+f"(c[3])
        : "r"(a0), "r"(a1), "r"(a2), "r"(a3), "r"(b0), "r"(b1));
}

__device__ __forceinline__ void cp16(unsigned int saddr, const void* gptr, int srcsize) {
    asm volatile("cp.async.ca.shared.global [%0], [%1], 16, %2;\n"
                 :: "r"(saddr), "l"(gptr), "r"(srcsize));
}
__device__ __forceinline__ void cp_commit() { asm volatile("cp.async.commit_group;\n"); }

// ---------------- shared-memory tiled tf32 GEMM body (cp.async double-buffered) ----------------
// C[M,Nn](ldc) = act(A[M,K](lda) @ B[K,Nn](ldb) + bias) (+resid[*,Nn]) for one 128x128 tile.
#define BK  16
#define AST 20
#define BST 136
__device__ __forceinline__ void gemm_body(
    const float* __restrict__ A, int lda,
    const float* __restrict__ B, int ldb,
    const float* __restrict__ bias,
    const float* __restrict__ resid,
    float* __restrict__ C, int ldc,
    int M, int Nn, int K, int act, int m0, int n0)
{
    __shared__ float As[2][128][AST];
    __shared__ float Bs[2][BK][BST];

    int tid = threadIdx.x;
    int wid = tid >> 5, lane = tid & 31;
    int wm0 = (wid & 3) * 32;
    int wn0 = (wid >> 2) * 64;
    int gid = lane >> 2, tig = lane & 3;

    // load coordinates
    int aRow = tid >> 2, aCol = (tid & 3) * 4;       // 64 rows per chunk, 2 chunks
    int bRow = tid >> 5, bCol = (tid & 31) * 4;      // 8 k-rows per chunk, 2 chunks

    const float* aPtr = A + (size_t)(m0 + aRow) * lda + aCol;
    const float* bPtr = B + (size_t)bRow * ldb + n0 + bCol;
    int aSz0 = (m0 + aRow < M) ? 16 : 0;
    int aSz1 = (m0 + aRow + 64 < M) ? 16 : 0;

    unsigned int aS[2][2], bS[2][2];
#pragma unroll
    for (int s = 0; s < 2; s++) {
        aS[s][0] = (unsigned int)__cvta_generic_to_shared(&As[s][aRow][aCol]);
        aS[s][1] = (unsigned int)__cvta_generic_to_shared(&As[s][aRow + 64][aCol]);
        bS[s][0] = (unsigned int)__cvta_generic_to_shared(&Bs[s][bRow][bCol]);
        bS[s][1] = (unsigned int)__cvta_generic_to_shared(&Bs[s][bRow + 8][bCol]);
    }

    float acc[2][8][4];
#pragma unroll
    for (int mi = 0; mi < 2; mi++)
#pragma unroll
        for (int ni = 0; ni < 8; ni++)
#pragma unroll
            for (int q = 0; q < 4; q++) acc[mi][ni][q] = 0.f;

    int niter = K / BK;

    // prologue: stage 0
    cp16(aS[0][0], aPtr, aSz0);
    cp16(aS[0][1], aPtr + (size_t)64 * lda, aSz1);
    cp16(bS[0][0], bPtr, 16);
    cp16(bS[0][1], bPtr + (size_t)8 * ldb, 16);
    cp_commit();
    aPtr += BK;
    bPtr += (size_t)BK * ldb;

    for (int i = 0; i < niter; i++) {
        if (i + 1 < niter) {
            int s = (i + 1) & 1;
            cp16(aS[s][0], aPtr, aSz0);
            cp16(aS[s][1], aPtr + (size_t)64 * lda, aSz1);
            cp16(bS[s][0], bPtr, 16);
            cp16(bS[s][1], bPtr + (size_t)8 * ldb, 16);
            cp_commit();
            aPtr += BK;
            bPtr += (size_t)BK * ldb;
            asm volatile("cp.async.wait_group 1;\n");
        } else {
            asm volatile("cp.async.wait_group 0;\n");
        }
        __syncthreads();

        int s = i & 1;
#pragma unroll
        for (int ks = 0; ks < 2; ks++) {
            int kk = ks * 8;
            unsigned a[2][4];
#pragma unroll
            for (int mi = 0; mi < 2; mi++) {
                int row = wm0 + mi * 16 + gid;
                a[mi][0] = __float_as_uint(As[s][row    ][kk + tig    ]);
                a[mi][1] = __float_as_uint(As[s][row + 8][kk + tig    ]);
                a[mi][2] = __float_as_uint(As[s][row    ][kk + tig + 4]);
                a[mi][3] = __float_as_uint(As[s][row + 8][kk + tig + 4]);
            }
            unsigned b[8][2];
#pragma unroll
            for (int ni = 0; ni < 8; ni++) {
                int col = wn0 + ni * 8 + gid;
                b[ni][0] = __float_as_uint(Bs[s][kk + tig    ][col]);
                b[ni][1] = __float_as_uint(Bs[s][kk + tig + 4][col]);
            }
#pragma unroll
            for (int mi = 0; mi < 2; mi++)
#pragma unroll
                for (int ni = 0; ni < 8; ni++)
                    mma_tf32(acc[mi][ni], a[mi][0], a[mi][1], a[mi][2], a[mi][3],
                             b[ni][0], b[ni][1]);
        }
        __syncthreads();
    }

    // epilogue
#pragma unroll
    for (int mi = 0; mi < 2; mi++) {
#pragma unroll
        for (int ni = 0; ni < 8; ni++) {
            int row = m0 + wm0 + mi * 16 + gid;
            int col = n0 + wn0 + ni * 8 + tig * 2;
            float bv0 = bias[col], bv1 = bias[col + 1];
#pragma unroll
            for (int half = 0; half < 2; half++) {
                int rr = row + half * 8;
                if (rr < M) {
                    float v0 = acc[mi][ni][half * 2 + 0] + bv0;
                    float v1 = acc[mi][ni][half * 2 + 1] + bv1;
                    if (act == 1) {
                        v0 = v0 / (1.f + expf(-v0));
                        v1 = v1 / (1.f + expf(-v1));
                    }
                    if (resid) {
                        v0 += resid[(size_t)rr * Nn + col];
                        v1 += resid[(size_t)rr * Nn + col + 1];
                    }
                    *reinterpret_cast<float2*>(&C[(size_t)rr * ldc + col]) = make_float2(v0, v1);
                }
            }
        }
    }
}

// ---------------- init ----------------
__global__ void init_kernel(int N, int P) {
    int i = blockIdx.x * blockDim.x + threadIdx.x;
    if (i < N * NREL * CDIM) d_agg[i] = 0.f;
    if (i < N * NREL * HEADS) { d_menc[i] = 0u; d_denom[i] = 0.f; }
    if (i < P) d_dsts[i] = -1;
    if (i < P * DE) d_eattrs[i] = 0.f;
    if (i < NREL) d_cnt[i] = 0;
}

// ---------------- counting sort by relation ----------------
__global__ void count_kernel(const int* __restrict__ etype, int E) {
    int i = blockIdx.x * blockDim.x + threadIdx.x;
    if (i < E) atomicAdd(&d_cnt[etype[i]], 1);
}
__global__ void offsets_kernel() {
    d_off[0] = 0;
    for (int r = 0; r < NREL; r++) {
        d_off[r + 1] = d_off[r] + ((d_cnt[r] + 127) & ~127);
        d_pos[r] = d_off[r];
    }
}
__global__ void scatter_kernel(const int* __restrict__ src, const int* __restrict__ dst,
                               const int* __restrict__ etype, const float* __restrict__ eattr,
                               int E) {
    int i = blockIdx.x * blockDim.x + threadIdx.x;
    if (i >= E) return;
    int r = etype[i];
    int p = atomicAdd(&d_pos[r], 1);
    d_srcs[p] = src[i];
    d_dsts[p] = dst[i];
    d_etys[p] = r;
    const float4* ia = reinterpret_cast<const float4*>(&eattr[(size_t)i * DE]);
    float4* oa = reinterpret_cast<float4*>(&d_eattrs[(size_t)p * DE]);
    oa[0] = ia[0]; oa[1] = ia[1]; oa[2] = ia[2]; oa[3] = ia[3];
}

// ---------------- e_base[r][hc] = rel_emb[r] @ W_e[r, De:, :] ----------------
__global__ void ebase_kernel(const float* __restrict__ rel_emb, const float* __restrict__ W_e) {
    int r = blockIdx.x;
    int hc = threadIdx.x;
    float s = 0.f;
#pragma unroll
    for (int d = 0; d < DRR; d++)
        s += rel_emb[r * DRR + d] * W_e[(r * DED + DE + d) * HCDIM + hc];
    d_ebase[r * HCDIM + hc] = s;
}

// ---------------- projections: one launch, z in [0,8) ----------------
__global__ __launch_bounds__(256) void proj_kernel(
    const float* __restrict__ Hm,
    const float* __restrict__ Wl, const float* __restrict__ bl,
    const float* __restrict__ Wr, const float* __restrict__ br, int N)
{
    int z = blockIdx.z;
    int r = z & (NREL - 1);
    const float* W; const float* bias; float* out;
    if (z < NREL) { W = Wl + (size_t)r * FDIM * HCDIM; bias = bl + r * HCDIM; out = d_XL + r * HCDIM; }
    else          { W = Wr + (size_t)r * FDIM * HCDIM; bias = br + r * HCDIM; out = d_XR + r * HCDIM; }
    gemm_body(Hm, FDIM, W, HCDIM, bias, nullptr, out, NREL * HCDIM,
              N, HCDIM, FDIM, 0, blockIdx.x * 128, blockIdx.y * 128);
}

// ---------------- e_feat GEMM over relation buckets ----------------
__global__ __launch_bounds__(256) void efeat_kernel(const float* __restrict__ W_e) {
    int m0 = blockIdx.x * 128;
    if (m0 >= d_off[NREL]) return;
    int r = 0;
#pragma unroll
    for (int q = 1; q < NREL; q++) if (m0 >= d_off[q]) r = q;
    gemm_body(d_eattrs, DE, W_e + (size_t)r * DED * HCDIM, HCDIM,
              d_ebase + r * HCDIM, nullptr, d_efeat, HCDIM,
              0x7fffffff, HCDIM, DE, 0, m0, blockIdx.y * 128);
}

// ---------------- generic GEMM (FFN) ----------------
__global__ __launch_bounds__(256) void gemm_tf32(
    const float* __restrict__ A, int lda,
    const float* __restrict__ B, int ldb,
    const float* __restrict__ bias, const float* __restrict__ resid,
    float* __restrict__ C, int ldc, int M, int Nn, int K, int act)
{
    gemm_body(A, lda, B, ldb, bias, resid, C, ldc, M, Nn, K, act,
              blockIdx.x * 128, blockIdx.y * 128);
}

// ---------------- scores + segment max (streams efeat) ----------------
__global__ void score_kernel(const float* __restrict__ att, int P)
{
    int warp = (blockIdx.x * blockDim.x + threadIdx.x) >> 5;
    int lane = threadIdx.x & 31;
    if (warp >= P) return;
    int e = warp;
    int d = d_dsts[e];
    if (d < 0) return;
    int r = d_etys[e];
    int s = d_srcs[e];

    const float* xl = d_XL + ((size_t)s * NREL + r) * HCDIM;
    const float* xr = d_XR + ((size_t)d * NREL + r) * HCDIM;
    const float* ef = d_efeat + (size_t)e * HCDIM;

    float hs[HEADS];
#pragma unroll
    for (int i = 0; i < HEADS; i++) {
        int hc = i * 128 + lane * 4;
        float4 vl = *reinterpret_cast<const float4*>(&xl[hc]);
        float4 vr = *reinterpret_cast<const float4*>(&xr[hc]);
        float4 vf = *reinterpret_cast<const float4*>(&ef[hc]);
        float x0 = vl.x + vr.x + vf.x; x0 = x0 > 0.f ? x0 : SLOPE * x0;
        float x1 = vl.y + vr.y + vf.y; x1 = x1 > 0.f ? x1 : SLOPE * x1;
        float x2 = vl.z + vr.z + vf.z; x2 = x2 > 0.f ? x2 : SLOPE * x2;
        float x3 = vl.w + vr.w + vf.w; x3 = x3 > 0.f ? x3 : SLOPE * x3;
        float4 a = *reinterpret_cast<const float4*>(&att[r * HCDIM + hc]);
        hs[i] = x0 * a.x + x1 * a.y + x2 * a.z + x3 * a.w;
    }
#pragma unroll
    for (int o = 16; o; o >>= 1) {
#pragma unroll
        for (int i = 0; i < HEADS; i++) hs[i] += __shfl_xor_sync(0xffffffffu, hs[i], o);
    }
    if (lane == 0) {
        int segb = (d * NREL + r) * HEADS;
#pragma unroll
        for (int h = 0; h < HEADS; h++) {
            d_alpha[(size_t)e * HEADS + h] = hs[h];
            atomicMax(&d_menc[segb + h], fenc(hs[h]));
        }
    }
}

// ---------------- exp(score - max), accumulate denom ----------------
__global__ void expsum_kernel(int P) {
    int idx = blockIdx.x * blockDim.x + threadIdx.x;
    if (idx >= P * HEADS) return;
    int e = idx >> 2;
    int h = idx & 3;
    int d = d_dsts[e];
    if (d < 0) return;
    int r = d_etys[e];
    int seg = (d * NREL + r) * HEADS + h;
    float m = fdec(d_menc[seg]);
    float a = expf(d_alpha[idx] - m);
    d_alpha[idx] = a;
    atomicAdd(&d_denom[seg], a);
}

// ---------------- aggregate ----------------
__global__ void agg_kernel(int P)
{
    int warp = (blockIdx.x * blockDim.x + threadIdx.x) >> 5;
    int lane = threadIdx.x & 31;
    if (warp >= P) return;
    int e = warp;
    int d = d_dsts[e];
    if (d < 0) return;
    int r = d_etys[e];
    int s = d_srcs[e];
    int segb = (d * NREL + r) * HEADS;

    float al[HEADS];
#pragma unroll
    for (int h = 0; h < HEADS; h++)
        al[h] = d_alpha[(size_t)e * HEADS + h] / d_denom[segb + h] * (1.f / HEADS);

    const float* xl = d_XL + ((size_t)s * NREL + r) * HCDIM;
    int c0 = lane * 4;
    float4 acc = make_float4(0.f, 0.f, 0.f, 0.f);
#pragma unroll
    for (int h = 0; h < HEADS; h++) {
        float4 v = *reinterpret_cast<const float4*>(&xl[h * CDIM + c0]);
        acc.x += al[h] * v.x; acc.y += al[h] * v.y;
        acc.z += al[h] * v.z; acc.w += al[h] * v.w;
    }
    float* outp = d_agg + ((size_t)d * NREL + r) * CDIM + c0;
    atomicAdd(outp + 0, acc.x);
    atomicAdd(outp + 1, acc.y);
    atomicAdd(outp + 2, acc.z);
    atomicAdd(outp + 3, acc.w);
}

// ---------------- gated fusion + residual + LayerNorm1 ----------------
__global__ void fuse1_kernel(const float* __restrict__ hin, const float* __restrict__ relbias,
                             const float* __restrict__ gate, const float* __restrict__ g1,
                             const float* __restrict__ bt1, int N)
{
    int n = blockIdx.x;
    if (n >= N) return;
    int c = threadIdx.x;

    float gv0 = __ldg(&gate[0]), gv1 = __ldg(&gate[1]), gv2 = __ldg(&gate[2]), gv3 = __ldg(&gate[3]);
    float gm = fmaxf(fmaxf(gv0, gv1), fmaxf(gv2, gv3));
    float e0 = expf(gv0 - gm), e1 = expf(gv1 - gm), e2 = expf(gv2 - gm), e3 = expf(gv3 - gm);
    float inv = 1.f / (e0 + e1 + e2 + e3);

    size_t ab = (size_t)n * NREL * CDIM;
    float t = hin[(size_t)n * FDIM + c]
            + e0 * inv * (d_agg[ab + 0 * CDIM + c] + relbias[0 * CDIM + c])
            + e1 * inv * (d_agg[ab + 1 * CDIM + c] + relbias[1 * CDIM + c])
            + e2 * inv * (d_agg[ab + 2 * CDIM + c] + relbias[2 * CDIM + c])
            + e3 * inv * (d_agg[ab + 3 * CDIM + c] + relbias[3 * CDIM + c]);

    __shared__ float sh1[4], sh2[4];
    float s1 = t, s2 = t * t;
#pragma unroll
    for (int o = 16; o; o >>= 1) {
        s1 += __shfl_xor_sync(0xffffffffu, s1, o);
        s2 += __shfl_xor_sync(0xffffffffu, s2, o);
    }
    if ((threadIdx.x & 31) == 0) { sh1[threadIdx.x >> 5] = s1; sh2[threadIdx.x >> 5] = s2; }
    __syncthreads();
    s1 = sh1[0] + sh1[1] + sh1[2] + sh1[3];
    s2 = sh2[0] + sh2[1] + sh2[2] + sh2[3];
    float mu = s1 * (1.f / FDIM);
    float var = s2 * (1.f / FDIM) - mu * mu;
    d_h1[(size_t)n * FDIM + c] = (t - mu) * rsqrtf(var + LN_EPS) * g1[c] + bt1[c];
}

// ---------------- final LayerNorm2 ----------------
__global__ void ln2_kernel(const float* __restrict__ g2, const float* __restrict__ bt2,
                           float* __restrict__ out, int N)
{
    int n = blockIdx.x;
    if (n >= N) return;
    int c = threadIdx.x;
    float t = d_y[(size_t)n * FDIM + c];

    __shared__ float sh1[4], sh2[4];
    float s1 = t, s2 = t * t;
#pragma unroll
    for (int o = 16; o; o >>= 1) {
        s1 += __shfl_xor_sync(0xffffffffu, s1, o);
        s2 += __shfl_xor_sync(0xffffffffu, s2, o);
    }
    if ((threadIdx.x & 31) == 0) { sh1[threadIdx.x >> 5] = s1; sh2[threadIdx.x >> 5] = s2; }
    __syncthreads();
    s1 = sh1[0] + sh1[1] + sh1[2] + sh1[3];
    s2 = sh2[0] + sh2[1] + sh2[2] + sh2[3];
    float mu = s1 * (1.f / FDIM);
    float var = s2 * (1.f / FDIM) - mu * mu;
    out[(size_t)n * FDIM + c] = (t - mu) * rsqrtf(var + LN_EPS) * g2[c] + bt2[c];
}

// ---------------- host launcher ----------------
extern "C" void kernel_launch(void* const* d_in, const int* in_sizes, int n_in,
                              void* d_out, int out_size)
{
    const float* h       = (const float*)d_in[0];
    const int*   eidx    = (const int*)  d_in[1];
    const float* eattr   = (const float*)d_in[2];
    const int*   etype   = (const int*)  d_in[3];
    const float* rel_emb = (const float*)d_in[4];
    const float* W_l     = (const float*)d_in[5];
    const float* b_l     = (const float*)d_in[6];
    const float* W_r     = (const float*)d_in[7];
    const float* b_r     = (const float*)d_in[8];
    const float* W_e     = (const float*)d_in[9];
    const float* att     = (const float*)d_in[10];
    const float* bias    = (const float*)d_in[11];
    const float* gate    = (const float*)d_in[12];
    const float* g1      = (const float*)d_in[13];
    const float* bt1     = (const float*)d_in[14];
    const float* g2      = (const float*)d_in[15];
    const float* bt2     = (const float*)d_in[16];
    const float* Wf1     = (const float*)d_in[17];
    const float* bf1     = (const float*)d_in[18];
    const float* Wf2     = (const float*)d_in[19];
    const float* bf2     = (const float*)d_in[20];
    float* out = (float*)d_out;

    int N = in_sizes[0] / FDIM;
    int E = in_sizes[3];
    int P = E + 512;
    const int* src = eidx;
    const int* dst = eidx + E;

    void *ph1 = nullptr, *pmid = nullptr, *py = nullptr;
    cudaGetSymbolAddress(&ph1, d_h1);
    cudaGetSymbolAddress(&pmid, d_mid);
    cudaGetSymbolAddress(&py, d_y);

    // 1. init (zero accumulators, pad markers, counts)
    {
        int total = N * NREL * CDIM;   // largest range
        init_kernel<<<(total + 255) / 256, 256>>>(N, P);
    }
    // 2. counting sort of edges by relation (128-aligned buckets)
    count_kernel<<<(E + 255) / 256, 256>>>(etype, E);
    offsets_kernel<<<1, 1>>>();
    scatter_kernel<<<(E + 255) / 256, 256>>>(src, dst, etype, eattr, E);
    // 3. rel-emb part of lin_edge
    ebase_kernel<<<NREL, HCDIM>>>(rel_emb, W_e);
    // 4. projections (single fused launch)
    {
        dim3 grid((N + 127) / 128, HCDIM / 128, 2 * NREL);
        proj_kernel<<<grid, 256>>>(h, W_l, b_l, W_r, b_r, N);
    }
    // 5. e_feat GEMM over relation buckets
    {
        dim3 grid((P + 127) / 128, HCDIM / 128);
        efeat_kernel<<<grid, 256>>>(W_e);
    }
    // 6. scores + segment max
    score_kernel<<<(P + 7) / 8, 256>>>(att, P);
    // 7. exp + denom
    expsum_kernel<<<(P * HEADS + 255) / 256, 256>>>(P);
    // 8. aggregation
    agg_kernel<<<(P + 7) / 8, 256>>>(P);
    // 9. fuse + LN1
    fuse1_kernel<<<N, 128>>>(h, bias, gate, g1, bt1, N);
    // 10. FFN up (silu)
    {
        dim3 grid((N + 127) / 128, FFND / 128);
        gemm_tf32<<<grid, 256>>>((const float*)ph1, FDIM, Wf1, FFND, bf1, nullptr,
                                 (float*)pmid, FFND, N, FFND, FDIM, 1);
    }
    // 11. FFN down + residual
    {
        dim3 grid((N + 127) / 128, FDIM / 128);
        gemm_tf32<<<grid, 256>>>((const float*)pmid, FFND, Wf2, FDIM, bf2, (const float*)ph1,
                                 (float*)py, FDIM, N, FDIM, FFND, 0);
    }
    // 12. LN2 -> out
    ln2_kernel<<<N, 128>>>(g2, bt2, out, N);
}

// round 4
// speedup vs baseline: 2.4194x; 1.1421x over previous
#include <cuda_runtime.h>
#include <math.h>

#define NREL   4
#define HEADS  4
#define CDIM   128
#define HCDIM  512
#define FDIM   128
#define DE     16
#define DRR    8
#define DED    (DE + DRR)
#define FFND   256
#define MAXN   40000
#define MAXE   150000
#define PMAX   (MAXE + 512)
#define LN_EPS 1e-5f
#define SLOPE  0.2f

// ---------------- scratch ----------------
static __device__ float        d_XL[(size_t)MAXN * NREL * HCDIM];
static __device__ float        d_XR[(size_t)MAXN * NREL * HCDIM];
static __device__ float        d_eattrs[(size_t)PMAX * DE];
static __device__ int          d_srcs[PMAX];
static __device__ int          d_dsts[PMAX];
static __device__ int          d_cnt[NREL];
static __device__ int          d_off[NREL + 1];
static __device__ int          d_pos[NREL];
static __device__ float        d_alpha[(size_t)PMAX * HEADS];
static __device__ unsigned int d_menc[(size_t)MAXN * NREL * HEADS];
static __device__ float        d_denom[(size_t)MAXN * NREL * HEADS];
static __device__ float        d_agg[(size_t)MAXN * NREL * CDIM];
static __device__ float        d_h1[(size_t)MAXN * FDIM];
static __device__ float        d_mid[(size_t)MAXN * FFND];
static __device__ float        d_y[(size_t)MAXN * FDIM];
static __device__ float        d_ebase[NREL * HCDIM];

__device__ __forceinline__ unsigned int fenc(float f) {
    unsigned int u = __float_as_uint(f);
    return (u & 0x80000000u) ? ~u : (u | 0x80000000u);
}
__device__ __forceinline__ float fdec(unsigned int u) {
    return (u & 0x80000000u) ? __uint_as_float(u & 0x7FFFFFFFu) : __uint_as_float(~u);
}

__device__ __forceinline__ void mma_tf32(float c[4],
                                         unsigned a0, unsigned a1, unsigned a2, unsigned a3,
                                         unsigned b0, unsigned b1) {
    asm volatile(
        "mma.sync.aligned.m16n8k8.row.col.f32.tf32.tf32.f32 "
        "{%0,%1,%2,%3}, {%4,%5,%6,%7}, {%8,%9}, {%0,%1,%2,%3};"
        : "+f"(c[0]), "+f"(c[1]), "+f"(c[2]), "+f"(c[3])
        : "r"(a0), "r"(a1), "r"(a2), "r"(a3), "r"(b0), "r"(b1));
}

__device__ __forceinline__ void cp16(unsigned int saddr, const void* gptr, int srcsize) {
    asm volatile("cp.async.ca.shared.global [%0], [%1], 16, %2;\n"
                 :: "r"(saddr), "l"(gptr), "r"(srcsize));
}
__device__ __forceinline__ void cp_commit() { asm volatile("cp.async.commit_group;\n"); }

// ---------------- tf32 GEMM body: 3-stage cp.async, 1 sync/iter ----------------
#define BK   16
#define AST  20
#define BST  136
#define NSTG 3
__device__ __forceinline__ void gemm_body(
    const float* __restrict__ A, int lda,
    const float* __restrict__ B, int ldb,
    const float* __restrict__ bias,
    const float* __restrict__ resid,
    float* __restrict__ C, int ldc,
    int M, int Nn, int K, int act, int m0, int n0)
{
    __shared__ float As[NSTG][128][AST];
    __shared__ float Bs[NSTG][BK][BST];

    int tid = threadIdx.x;
    int wid = tid >> 5, lane = tid & 31;
    int wm0 = (wid & 3) * 32;
    int wn0 = (wid >> 2) * 64;
    int gid = lane >> 2, tig = lane & 3;

    int aRow = tid >> 2, aCol = (tid & 3) * 4;
    int bRow = tid >> 5, bCol = (tid & 31) * 4;

    const float* aPtr = A + (size_t)(m0 + aRow) * lda + aCol;
    const float* bPtr = B + (size_t)bRow * ldb + n0 + bCol;
    int aSz0 = (m0 + aRow < M) ? 16 : 0;
    int aSz1 = (m0 + aRow + 64 < M) ? 16 : 0;

    unsigned int aS[NSTG][2], bS[NSTG][2];
#pragma unroll
    for (int s = 0; s < NSTG; s++) {
        aS[s][0] = (unsigned int)__cvta_generic_to_shared(&As[s][aRow][aCol]);
        aS[s][1] = (unsigned int)__cvta_generic_to_shared(&As[s][aRow + 64][aCol]);
        bS[s][0] = (unsigned int)__cvta_generic_to_shared(&Bs[s][bRow][bCol]);
        bS[s][1] = (unsigned int)__cvta_generic_to_shared(&Bs[s][bRow + 8][bCol]);
    }

    float acc[2][8][4];
#pragma unroll
    for (int mi = 0; mi < 2; mi++)
#pragma unroll
        for (int ni = 0; ni < 8; ni++)
#pragma unroll
            for (int q = 0; q < 4; q++) acc[mi][ni][q] = 0.f;

    int niter = K / BK;

    // prologue: stages 0 and 1
#pragma unroll
    for (int s = 0; s < 2; s++) {
        cp16(aS[s][0], aPtr, aSz0);
        cp16(aS[s][1], aPtr + (size_t)64 * lda, aSz1);
        cp16(bS[s][0], bPtr, 16);
        cp16(bS[s][1], bPtr + (size_t)8 * ldb, 16);
        cp_commit();
        aPtr += BK;
        bPtr += (size_t)BK * ldb;
    }

    int s = 0;
    for (int i = 0; i < niter; i++) {
        asm volatile("cp.async.wait_group 1;\n");
        __syncthreads();

#pragma unroll
        for (int ks = 0; ks < 2; ks++) {
            int kk = ks * 8;
            unsigned a[2][4];
#pragma unroll
            for (int mi = 0; mi < 2; mi++) {
                int row = wm0 + mi * 16 + gid;
                a[mi][0] = __float_as_uint(As[s][row    ][kk + tig    ]);
                a[mi][1] = __float_as_uint(As[s][row + 8][kk + tig    ]);
                a[mi][2] = __float_as_uint(As[s][row    ][kk + tig + 4]);
                a[mi][3] = __float_as_uint(As[s][row + 8][kk + tig + 4]);
            }
            unsigned b[8][2];
#pragma unroll
            for (int ni = 0; ni < 8; ni++) {
                int col = wn0 + ni * 8 + gid;
                b[ni][0] = __float_as_uint(Bs[s][kk + tig    ][col]);
                b[ni][1] = __float_as_uint(Bs[s][kk + tig + 4][col]);
            }
#pragma unroll
            for (int mi = 0; mi < 2; mi++)
#pragma unroll
                for (int ni = 0; ni < 8; ni++)
                    mma_tf32(acc[mi][ni], a[mi][0], a[mi][1], a[mi][2], a[mi][3],
                             b[ni][0], b[ni][1]);
        }

        if (i + 2 < niter) {
            int sn = (s + 2) % NSTG;
            cp16(aS[sn][0], aPtr, aSz0);
            cp16(aS[sn][1], aPtr + (size_t)64 * lda, aSz1);
            cp16(bS[sn][0], bPtr, 16);
            cp16(bS[sn][1], bPtr + (size_t)8 * ldb, 16);
            cp_commit();
            aPtr += BK;
            bPtr += (size_t)BK * ldb;
        } else {
            cp_commit();  // keep group count in step for wait_group 1
        }
        s = (s + 1) % NSTG;
    }

    // epilogue
#pragma unroll
    for (int mi = 0; mi < 2; mi++) {
#pragma unroll
        for (int ni = 0; ni < 8; ni++) {
            int row = m0 + wm0 + mi * 16 + gid;
            int col = n0 + wn0 + ni * 8 + tig * 2;
            float bv0 = bias[col], bv1 = bias[col + 1];
#pragma unroll
            for (int half = 0; half < 2; half++) {
                int rr = row + half * 8;
                if (rr < M) {
                    float v0 = acc[mi][ni][half * 2 + 0] + bv0;
                    float v1 = acc[mi][ni][half * 2 + 1] + bv1;
                    if (act == 1) {
                        v0 = v0 / (1.f + expf(-v0));
                        v1 = v1 / (1.f + expf(-v1));
                    }
                    if (resid) {
                        v0 += resid[(size_t)rr * Nn + col];
                        v1 += resid[(size_t)rr * Nn + col + 1];
                    }
                    *reinterpret_cast<float2*>(&C[(size_t)rr * ldc + col]) = make_float2(v0, v1);
                }
            }
        }
    }
}

// ---------------- init ----------------
__global__ void init_kernel(int N, int P) {
    int i = blockIdx.x * blockDim.x + threadIdx.x;
    if (i < N * NREL * CDIM) d_agg[i] = 0.f;
    if (i < N * NREL * HEADS) { d_menc[i] = 0u; d_denom[i] = 0.f; }
    if (i < P) d_dsts[i] = -1;
    if (i < NREL) d_cnt[i] = 0;
}

// ---------------- counting sort (block-local histograms) ----------------
__global__ void count_kernel(const int* __restrict__ etype, int E) {
    __shared__ int c[NREL];
    int tid = threadIdx.x;
    if (tid < NREL) c[tid] = 0;
    __syncthreads();
    int i = blockIdx.x * blockDim.x + tid;
    if (i < E) atomicAdd(&c[etype[i]], 1);
    __syncthreads();
    if (tid < NREL) atomicAdd(&d_cnt[tid], c[tid]);
}
__global__ void offsets_kernel() {
    d_off[0] = 0;
    for (int r = 0; r < NREL; r++) {
        d_off[r + 1] = d_off[r] + ((d_cnt[r] + 127) & ~127);
        d_pos[r] = d_off[r];
    }
}
__global__ void scatter_kernel(const int* __restrict__ src, const int* __restrict__ dst,
                               const int* __restrict__ etype, const float* __restrict__ eattr,
                               int E) {
    __shared__ int c[NREL], base[NREL];
    int tid = threadIdx.x;
    if (tid < NREL) c[tid] = 0;
    __syncthreads();
    int i = blockIdx.x * blockDim.x + tid;
    int r = -1, myr = 0;
    if (i < E) { r = etype[i]; myr = atomicAdd(&c[r], 1); }
    __syncthreads();
    if (tid < NREL) base[tid] = atomicAdd(&d_pos[tid], c[tid]);
    __syncthreads();
    if (i < E) {
        int p = base[r] + myr;
        d_srcs[p] = src[i];
        d_dsts[p] = dst[i];
        const float4* ia = reinterpret_cast<const float4*>(&eattr[(size_t)i * DE]);
        float4* oa = reinterpret_cast<float4*>(&d_eattrs[(size_t)p * DE]);
        oa[0] = ia[0]; oa[1] = ia[1]; oa[2] = ia[2]; oa[3] = ia[3];
    }
}

// ---------------- e_base ----------------
__global__ void ebase_kernel(const float* __restrict__ rel_emb, const float* __restrict__ W_e) {
    int r = blockIdx.x;
    int hc = threadIdx.x;
    float s = 0.f;
#pragma unroll
    for (int d = 0; d < DRR; d++)
        s += rel_emb[r * DRR + d] * W_e[(r * DED + DE + d) * HCDIM + hc];
    d_ebase[r * HCDIM + hc] = s;
}

// ---------------- projections (fused launch, z in [0,8)) ----------------
__global__ __launch_bounds__(256) void proj_kernel(
    const float* __restrict__ Hm,
    const float* __restrict__ Wl, const float* __restrict__ bl,
    const float* __restrict__ Wr, const float* __restrict__ br, int N)
{
    int z = blockIdx.z;
    int r = z & (NREL - 1);
    const float* W; const float* bias; float* out;
    if (z < NREL) { W = Wl + (size_t)r * FDIM * HCDIM; bias = bl + r * HCDIM; out = d_XL + r * HCDIM; }
    else          { W = Wr + (size_t)r * FDIM * HCDIM; bias = br + r * HCDIM; out = d_XR + r * HCDIM; }
    gemm_body(Hm, FDIM, W, HCDIM, bias, nullptr, out, NREL * HCDIM,
              N, HCDIM, FDIM, 0, blockIdx.x * 128, blockIdx.y * 128);
}

// ---------------- generic GEMM (FFN) ----------------
__global__ __launch_bounds__(256) void gemm_tf32(
    const float* __restrict__ A, int lda,
    const float* __restrict__ B, int ldb,
    const float* __restrict__ bias, const float* __restrict__ resid,
    float* __restrict__ C, int ldc, int M, int Nn, int K, int act)
{
    gemm_body(A, lda, B, ldb, bias, resid, C, ldc, M, Nn, K, act,
              blockIdx.x * 128, blockIdx.y * 128);
}

// ---------------- fused score: e_feat from smem W_e + xl + xr -> attention + seg max ----------------
#define SBLK 16   // edges per block (one warp each), 512 threads
__global__ __launch_bounds__(512) void score_kernel(
    const float* __restrict__ att, const float* __restrict__ W_e, int P)
{
    __shared__ float sWe[DE][HCDIM];   // 32 KB
    __shared__ float sEb[HCDIM];       //  2 KB

    int e0 = blockIdx.x * SBLK;
    int r = 0;
#pragma unroll
    for (int q = 1; q < NREL; q++) if (e0 >= d_off[q]) r = q;

    // cooperative smem staging
    const float4* wsrc = reinterpret_cast<const float4*>(W_e + (size_t)r * DED * HCDIM);
    float4* wdst = reinterpret_cast<float4*>(&sWe[0][0]);
    for (int i = threadIdx.x; i < DE * HCDIM / 4; i += 512) wdst[i] = wsrc[i];
    const float4* esrc = reinterpret_cast<const float4*>(d_ebase + r * HCDIM);
    float4* edst = reinterpret_cast<float4*>(sEb);
    for (int i = threadIdx.x; i < HCDIM / 4; i += 512) edst[i] = esrc[i];
    __syncthreads();

    int wi = threadIdx.x >> 5;
    int lane = threadIdx.x & 31;
    int e = e0 + wi;
    int d = (e < P) ? d_dsts[e] : -1;
    if (d >= 0) {
        int s = d_srcs[e];
        const float* xl = d_XL + ((size_t)s * NREL + r) * HCDIM;
        const float* xr = d_XR + ((size_t)d * NREL + r) * HCDIM;

        float ea[DE];
#pragma unroll
        for (int k = 0; k < DE; k++) ea[k] = d_eattrs[(size_t)e * DE + k];

        float hs[HEADS];
#pragma unroll
        for (int i = 0; i < HEADS; i++) {
            int hc = i * 128 + lane * 4;
            float4 ef = *reinterpret_cast<const float4*>(&sEb[hc]);
#pragma unroll
            for (int k = 0; k < DE; k++) {
                float4 w = *reinterpret_cast<const float4*>(&sWe[k][hc]);
                ef.x += ea[k] * w.x; ef.y += ea[k] * w.y;
                ef.z += ea[k] * w.z; ef.w += ea[k] * w.w;
            }
            float4 vl = *reinterpret_cast<const float4*>(&xl[hc]);
            float4 vr = *reinterpret_cast<const float4*>(&xr[hc]);
            float x0 = vl.x + vr.x + ef.x; x0 = x0 > 0.f ? x0 : SLOPE * x0;
            float x1 = vl.y + vr.y + ef.y; x1 = x1 > 0.f ? x1 : SLOPE * x1;
            float x2 = vl.z + vr.z + ef.z; x2 = x2 > 0.f ? x2 : SLOPE * x2;
            float x3 = vl.w + vr.w + ef.w; x3 = x3 > 0.f ? x3 : SLOPE * x3;
            float4 a = *reinterpret_cast<const float4*>(&att[r * HCDIM + hc]);
            hs[i] = x0 * a.x + x1 * a.y + x2 * a.z + x3 * a.w;
        }
#pragma unroll
        for (int o = 16; o; o >>= 1) {
#pragma unroll
            for (int i = 0; i < HEADS; i++) hs[i] += __shfl_xor_sync(0xffffffffu, hs[i], o);
        }
        if (lane == 0) {
            int segb = (d * NREL + r) * HEADS;
#pragma unroll
            for (int h = 0; h < HEADS; h++) {
                d_alpha[(size_t)e * HEADS + h] = hs[h];
                atomicMax(&d_menc[segb + h], fenc(hs[h]));
            }
        }
    }
}

// ---------------- exp(score - max), accumulate denom ----------------
__global__ void expsum_kernel(int P) {
    int idx = blockIdx.x * blockDim.x + threadIdx.x;
    if (idx >= P * HEADS) return;
    int e = idx >> 2;
    int h = idx & 3;
    int d = d_dsts[e];
    if (d < 0) return;
    int r = 0;
#pragma unroll
    for (int q = 1; q < NREL; q++) if (e >= d_off[q]) r = q;
    int seg = (d * NREL + r) * HEADS + h;
    float m = fdec(d_menc[seg]);
    float a = expf(d_alpha[idx] - m);
    d_alpha[idx] = a;
    atomicAdd(&d_denom[seg], a);
}

// ---------------- aggregate ----------------
__global__ void agg_kernel(int P)
{
    int warp = (blockIdx.x * blockDim.x + threadIdx.x) >> 5;
    int lane = threadIdx.x & 31;
    if (warp >= P) return;
    int e = warp;
    int d = d_dsts[e];
    if (d < 0) return;
    int r = 0;
#pragma unroll
    for (int q = 1; q < NREL; q++) if (e >= d_off[q]) r = q;
    int s = d_srcs[e];
    int segb = (d * NREL + r) * HEADS;

    float al[HEADS];
#pragma unroll
    for (int h = 0; h < HEADS; h++)
        al[h] = d_alpha[(size_t)e * HEADS + h] / d_denom[segb + h] * (1.f / HEADS);

    const float* xl = d_XL + ((size_t)s * NREL + r) * HCDIM;
    int c0 = lane * 4;
    float4 acc = make_float4(0.f, 0.f, 0.f, 0.f);
#pragma unroll
    for (int h = 0; h < HEADS; h++) {
        float4 v = *reinterpret_cast<const float4*>(&xl[h * CDIM + c0]);
        acc.x += al[h] * v.x; acc.y += al[h] * v.y;
        acc.z += al[h] * v.z; acc.w += al[h] * v.w;
    }
    float* outp = d_agg + ((size_t)d * NREL + r) * CDIM + c0;
    atomicAdd(outp + 0, acc.x);
    atomicAdd(outp + 1, acc.y);
    atomicAdd(outp + 2, acc.z);
    atomicAdd(outp + 3, acc.w);
}

// ---------------- gated fusion + residual + LayerNorm1 ----------------
__global__ void fuse1_kernel(const float* __restrict__ hin, const float* __restrict__ relbias,
                             const float* __restrict__ gate, const float* __restrict__ g1,
                             const float* __restrict__ bt1, int N)
{
    int n = blockIdx.x;
    if (n >= N) return;
    int c = threadIdx.x;

    float gv0 = __ldg(&gate[0]), gv1 = __ldg(&gate[1]), gv2 = __ldg(&gate[2]), gv3 = __ldg(&gate[3]);
    float gm = fmaxf(fmaxf(gv0, gv1), fmaxf(gv2, gv3));
    float e0 = expf(gv0 - gm), e1 = expf(gv1 - gm), e2 = expf(gv2 - gm), e3 = expf(gv3 - gm);
    float inv = 1.f / (e0 + e1 + e2 + e3);

    size_t ab = (size_t)n * NREL * CDIM;
    float t = hin[(size_t)n * FDIM + c]
            + e0 * inv * (d_agg[ab + 0 * CDIM + c] + relbias[0 * CDIM + c])
            + e1 * inv * (d_agg[ab + 1 * CDIM + c] + relbias[1 * CDIM + c])
            + e2 * inv * (d_agg[ab + 2 * CDIM + c] + relbias[2 * CDIM + c])
            + e3 * inv * (d_agg[ab + 3 * CDIM + c] + relbias[3 * CDIM + c]);

    __shared__ float sh1[4], sh2[4];
    float s1 = t, s2 = t * t;
#pragma unroll
    for (int o = 16; o; o >>= 1) {
        s1 += __shfl_xor_sync(0xffffffffu, s1, o);
        s2 += __shfl_xor_sync(0xffffffffu, s2, o);
    }
    if ((threadIdx.x & 31) == 0) { sh1[threadIdx.x >> 5] = s1; sh2[threadIdx.x >> 5] = s2; }
    __syncthreads();
    s1 = sh1[0] + sh1[1] + sh1[2] + sh1[3];
    s2 = sh2[0] + sh2[1] + sh2[2] + sh2[3];
    float mu = s1 * (1.f / FDIM);
    float var = s2 * (1.f / FDIM) - mu * mu;
    d_h1[(size_t)n * FDIM + c] = (t - mu) * rsqrtf(var + LN_EPS) * g1[c] + bt1[c];
}

// ---------------- final LayerNorm2 ----------------
__global__ void ln2_kernel(const float* __restrict__ g2, const float* __restrict__ bt2,
                           float* __restrict__ out, int N)
{
    int n = blockIdx.x;
    if (n >= N) return;
    int c = threadIdx.x;
    float t = d_y[(size_t)n * FDIM + c];

    __shared__ float sh1[4], sh2[4];
    float s1 = t, s2 = t * t;
#pragma unroll
    for (int o = 16; o; o >>= 1) {
        s1 += __shfl_xor_sync(0xffffffffu, s1, o);
        s2 += __shfl_xor_sync(0xffffffffu, s2, o);
    }
    if ((threadIdx.x & 31) == 0) { sh1[threadIdx.x >> 5] = s1; sh2[threadIdx.x >> 5] = s2; }
    __syncthreads();
    s1 = sh1[0] + sh1[1] + sh1[2] + sh1[3];
    s2 = sh2[0] + sh2[1] + sh2[2] + sh2[3];
    float mu = s1 * (1.f / FDIM);
    float var = s2 * (1.f / FDIM) - mu * mu;
    out[(size_t)n * FDIM + c] = (t - mu) * rsqrtf(var + LN_EPS) * g2[c] + bt2[c];
}

// ---------------- host launcher ----------------
extern "C" void kernel_launch(void* const* d_in, const int* in_sizes, int n_in,
                              void* d_out, int out_size)
{
    const float* h       = (const float*)d_in[0];
    const int*   eidx    = (const int*)  d_in[1];
    const float* eattr   = (const float*)d_in[2];
    const int*   etype   = (const int*)  d_in[3];
    const float* rel_emb = (const float*)d_in[4];
    const float* W_l     = (const float*)d_in[5];
    const float* b_l     = (const float*)d_in[6];
    const float* W_r     = (const float*)d_in[7];
    const float* b_r     = (const float*)d_in[8];
    const float* W_e     = (const float*)d_in[9];
    const float* att     = (const float*)d_in[10];
    const float* bias    = (const float*)d_in[11];
    const float* gate    = (const float*)d_in[12];
    const float* g1      = (const float*)d_in[13];
    const float* bt1     = (const float*)d_in[14];
    const float* g2      = (const float*)d_in[15];
    const float* bt2     = (const float*)d_in[16];
    const float* Wf1     = (const float*)d_in[17];
    const float* bf1     = (const float*)d_in[18];
    const float* Wf2     = (const float*)d_in[19];
    const float* bf2     = (const float*)d_in[20];
    float* out = (float*)d_out;

    int N = in_sizes[0] / FDIM;
    int E = in_sizes[3];
    int P = E + 512;
    const int* src = eidx;
    const int* dst = eidx + E;

    void *ph1 = nullptr, *pmid = nullptr, *py = nullptr;
    cudaGetSymbolAddress(&ph1, d_h1);
    cudaGetSymbolAddress(&pmid, d_mid);
    cudaGetSymbolAddress(&py, d_y);

    // 1. init
    {
        int total = N * NREL * CDIM;
        init_kernel<<<(total + 255) / 256, 256>>>(N, P);
    }
    // 2. sort edges by relation
    count_kernel<<<(E + 255) / 256, 256>>>(etype, E);
    offsets_kernel<<<1, 1>>>();
    scatter_kernel<<<(E + 255) / 256, 256>>>(src, dst, etype, eattr, E);
    // 3. rel-emb part of lin_edge
    ebase_kernel<<<NREL, HCDIM>>>(rel_emb, W_e);
    // 4. projections
    {
        dim3 grid((N + 127) / 128, HCDIM / 128, 2 * NREL);
        proj_kernel<<<grid, 256>>>(h, W_l, b_l, W_r, b_r, N);
    }
    // 5. fused e_feat + scores + segment max
    score_kernel<<<(P + SBLK - 1) / SBLK, 512>>>(att, W_e, P);
    // 6. exp + denom
    expsum_kernel<<<(P * HEADS + 255) / 256, 256>>>(P);
    // 7. aggregation
    agg_kernel<<<(P + 7) / 8, 256>>>(P);
    // 8. fuse + LN1
    fuse1_kernel<<<N, 128>>>(h, bias, gate, g1, bt1, N);
    // 9. FFN up (silu)
    {
        dim3 grid((N + 127) / 128, FFND / 128);
        gemm_tf32<<<grid, 256>>>((const float*)ph1, FDIM, Wf1, FFND, bf1, nullptr,
                                 (float*)pmid, FFND, N, FFND, FDIM, 1);
    }
    // 10. FFN down + residual
    {
        dim3 grid((N + 127) / 128, FDIM / 128);
        gemm_tf32<<<grid, 256>>>((const float*)pmid, FFND, Wf2, FDIM, bf2, (const float*)ph1,
                                 (float*)py, FDIM, N, FDIM, FFND, 0);
    }
    // 11. LN2 -> out
    ln2_kernel<<<N, 128>>>(g2, bt2, out, N);
}